// round 15
// baseline (speedup 1.0000x reference)
#include <cuda_runtime.h>
#include <math.h>

#define NFEAT   2000
#define TOTCAND 13280
#define MAXHW   (1024*1024)
#define LVS     (2*MAXHW)
#define EPSF    1e-8f
#define CANDCAP 4096
#define SORTN   4096
#define C1CAP   262144
#define BX 32
#define BY 8
#define BYO 16

// ---------------- static device scratch ----------------
__device__ float g_lv[5][LVS];
__device__ float g_resp[5][LVS];
__device__ float g_e[5][LVS];
__device__ float g_vals[5][LVS];

__device__ unsigned g_bins[2][256];
__device__ unsigned g_candcnt[2];
__device__ unsigned g_cnt1[2];
__device__ unsigned g_cand1[2][C1CAP];
__device__ unsigned g_candlist[2][CANDCAP];
__device__ unsigned g_selidx[2][NFEAT];
__device__ float    g_selval[2][NFEAT];
__device__ float    g_cand_resp[2][TOTCAND];
__device__ float    g_cand_laf[2][TOTCAND][6];
__device__ unsigned g_finidx[2][NFEAT];
__device__ float    g_finval[2][NFEAT];

struct KW { float w[24]; };   // blur weights passed by value (const bank)

// Hessian kernels (reference _K2 / abs-sum: /64, /36, /64; f32-exact constants)
__constant__ float cGXX[25] = {
 -1.f/64,0.f,2.f/64,0.f,-1.f/64, -4.f/64,0.f,8.f/64,0.f,-4.f/64,
 -6.f/64,0.f,12.f/64,0.f,-6.f/64, -4.f/64,0.f,8.f/64,0.f,-4.f/64,
 -1.f/64,0.f,2.f/64,0.f,-1.f/64 };
__constant__ float cGXY[25] = {
 (float)(-1.0/36),(float)(-2.0/36),0.f,(float)(2.0/36),(float)(1.0/36),
 (float)(-2.0/36),(float)(-4.0/36),0.f,(float)(4.0/36),(float)(2.0/36),
 0.f,0.f,0.f,0.f,0.f,
 (float)(2.0/36),(float)(4.0/36),0.f,(float)(-4.0/36),(float)(-2.0/36),
 (float)(1.0/36),(float)(2.0/36),0.f,(float)(-2.0/36),(float)(-1.0/36) };
__constant__ float cGYY[25] = {     // _GXX.T
 -1.f/64,-4.f/64,-6.f/64,-4.f/64,-1.f/64, 0.f,0.f,0.f,0.f,0.f,
 2.f/64,8.f/64,12.f/64,8.f/64,2.f/64, 0.f,0.f,0.f,0.f,0.f,
 -1.f/64,-4.f/64,-6.f/64,-4.f/64,-1.f/64 };

// XLA-CPU inline exp (Cephes), every mul/add UNFUSED — bit-exact
__device__ __forceinline__ float xla_expf(float input){
  float x = fminf(input, 88.3762626647950f);
  x = fmaxf(x, -88.3762626647949f);
  float fx = floorf(__fadd_rn(__fmul_rn(x, 1.44269504088896341f), 0.5f));
  float tmp = __fmul_rn(fx, 0.693359375f);
  float z   = __fmul_rn(fx, -2.12194440e-4f);
  x = __fsub_rn(x, tmp);
  x = __fsub_rn(x, z);
  float z2 = __fmul_rn(x, x);
  float y = 1.9875691500E-4f;
  y = __fadd_rn(__fmul_rn(y, x), 1.3981999507E-3f);
  y = __fadd_rn(__fmul_rn(y, x), 8.3334519073E-3f);
  y = __fadd_rn(__fmul_rn(y, x), 4.1665795894E-2f);
  y = __fadd_rn(__fmul_rn(y, x), 1.6666665459E-1f);
  y = __fadd_rn(__fmul_rn(y, x), 5.0000001201E-1f);
  y = __fadd_rn(__fmul_rn(y, z2), x);
  y = __fadd_rn(y, 1.0f);
  int n = (int)fx;
  float p2n = __uint_as_float((unsigned)(n + 127) << 23);
  return __fmul_rn(y, p2n);
}

__device__ __forceinline__ unsigned fkey(float f){
  unsigned u = __float_as_uint(f);
  if ((u << 1) == 0u) return 0x80000000u;
  return (u & 0x80000000u) ? ~u : (u | 0x80000000u);
}

__device__ __forceinline__ float cand_val(int mode, int b, unsigned i, int HW){
  if (mode == 0){
    unsigned d = i / (unsigned)HW;
    return g_vals[d][(unsigned)b*HW + (i - d*(unsigned)HW)];
  }
  return g_cand_resp[b][i];
}

// ---------------- fused separable blur ----------------
// vertical into smem (columns incl. P halo, reflect-mapped), then horizontal.
// sv[ry][tx+i] == unfused g_tmp[r(x+i-P)] bit-exactly (same tap sequence).
// Fill guard: only columns with unreflected gx <= W-1+P are ever read by the
// horizontal pass; beyond that single reflection breaks (gx >= 2W-2) -> skip.
template<int N>
__global__ void k_blur2(const float* __restrict__ src, float* __restrict__ dst,
                        int H,int W, KW kw){
  const int P = N/2;
  int x0 = blockIdx.x*BX, y0 = blockIdx.y*BYO, b = blockIdx.z;
  const float* s = src + (size_t)b*H*W;
  __shared__ float sv[BYO][BX + 2*10 + 1];
  const int ncols = BX + 2*P;
  int tid = threadIdx.y*BX + threadIdx.x;
  for (int tsk = tid; tsk < ncols*BYO; tsk += BX*BY){
    int cc = tsk % ncols, ry = tsk / ncols;
    int y = y0 + ry;
    if (y >= H) continue;
    int gx = x0 + cc - P;
    if (gx >= W + P) continue;              // never read; reflection invalid
    gx = (gx<0) ? -gx : ((gx>=W) ? (2*W-2-gx) : gx);
    float acc = 0.f;
    if (y >= P && y + P < H){
      #pragma unroll
      for (int i=0;i<N;i++)
        acc = __fadd_rn(acc, __fmul_rn(kw.w[i], s[(y+i-P)*W + gx]));
    } else {
      #pragma unroll
      for (int i=0;i<N;i++){
        int t = y+i-P;
        t = (t<0) ? -t : ((t>=H) ? (2*H-2-t) : t);
        acc = __fadd_rn(acc, __fmul_rn(kw.w[i], s[t*W + gx]));
      }
    }
    sv[ry][cc] = acc;
  }
  __syncthreads();
  int x = x0 + threadIdx.x;
  if (x >= W) return;
  for (int ry = threadIdx.y; ry < BYO; ry += BY){
    int y = y0 + ry;
    if (y >= H) continue;
    float acc = 0.f;
    #pragma unroll
    for (int i=0;i<N;i++)
      acc = __fadd_rn(acc, __fmul_rn(kw.w[i], sv[ry][threadIdx.x + i]));
    dst[(size_t)b*H*W + y*W + x] = acc;
  }
}

__global__ void k_down(int S){
  int idx = blockIdx.x*blockDim.x + threadIdx.x;
  int HW = S*S, tot = 2*HW; if (idx >= tot) return;
  int b = idx/HW, rem = idx-b*HW;
  int y = rem/S, x = rem-(rem/S)*S;
  int S2 = 2*S, HW2 = 4*HW;
  g_lv[0][idx] = g_lv[3][b*HW2 + (2*y)*S2 + 2*x];
}

// ---------------- hessian: smem-tiled, kh outer / kw inner, UNFUSED ----------------
__global__ void k_hess2(int H,int W,float q0,float q1,float q2,float q3,float q4){
  int l = blockIdx.z % 5, b = blockIdx.z / 5;
  int x0 = blockIdx.x*BX, y0 = blockIdx.y*BY;
  __shared__ float t[BY+4][BX+4];
  const float* s = &g_lv[l][b*H*W];
  for (int j = threadIdx.y; j < BY+4; j += BY){
    int yy = y0 + j - 2; yy = yy<0?0:(yy>H-1?H-1:yy);
    for (int i = threadIdx.x; i < BX+4; i += BX){
      int xx = x0 + i - 2; xx = xx<0?0:(xx>W-1?W-1:xx);
      t[j][i] = s[yy*W+xx];
    }
  }
  __syncthreads();
  int x = x0 + threadIdx.x, y = y0 + threadIdx.y;
  if (x >= W || y >= H) return;
  float dxx=0.f,dxy=0.f,dyy=0.f;
  #pragma unroll
  for (int i=0;i<5;i++){
    #pragma unroll
    for (int j=0;j<5;j++){
      float pv = t[threadIdx.y+i][threadIdx.x+j];
      dxx = __fadd_rn(dxx, __fmul_rn(cGXX[i*5+j], pv));
      dxy = __fadd_rn(dxy, __fmul_rn(cGXY[i*5+j], pv));
      dyy = __fadd_rn(dyy, __fmul_rn(cGYY[i*5+j], pv));
    }
  }
  float s4 = (l==0)?q0:(l==1)?q1:(l==2)?q2:(l==3)?q3:q4;
  float det = __fsub_rn(__fmul_rn(dxx,dyy), __fmul_rn(dxy,dxy));
  g_resp[l][(size_t)b*H*W + y*W + x] = __fmul_rn(det, s4);
}

// ---------------- emap: tiled 3 planes, -FLT_MAX pad (max exact) ----------------
__global__ void k_emap2(int H,int W){
  int l = blockIdx.z % 5, b = blockIdx.z / 5;
  int x0 = blockIdx.x*BX, y0 = blockIdx.y*BY;
  int HW = H*W;
  __shared__ float t[3][BY+2][BX+2];
  for (int p=0;p<3;p++){
    int dd = l-1+p;
    bool pv = (dd>=0 && dd<=4);
    const float* rp = pv ? &g_resp[dd][b*HW] : 0;
    for (int j = threadIdx.y; j < BY+2; j += BY){
      int gy = y0 - 1 + j;
      for (int i = threadIdx.x; i < BX+2; i += BX){
        int gx = x0 - 1 + i;
        bool ok = pv && gy>=0 && gy<H && gx>=0 && gx<W;
        t[p][j][i] = ok ? rp[gy*W+gx] : -3.402823466e38f;
      }
    }
  }
  __syncthreads();
  int x = x0 + threadIdx.x, y = y0 + threadIdx.y;
  if (x >= W || y >= H) return;
  float m = -3.402823466e38f;
  #pragma unroll
  for (int p=0;p<3;p++)
    #pragma unroll
    for (int j=0;j<3;j++)
      #pragma unroll
      for (int i=0;i<3;i++)
        m = fmaxf(m, t[p][threadIdx.y+j][threadIdx.x+i]);
  float c = t[1][threadIdx.y+1][threadIdx.x+1];
  g_e[l][b*HW + y*W + x] = xla_expf(__fsub_rn(c, m));
}

// ---------------- vals: tiled, +0 pad (exact no-op), fused round-0 hist ----------
__global__ void k_vals2(int H,int W){
  int l = blockIdx.z % 5, b = blockIdx.z / 5;
  int x0 = blockIdx.x*BX, y0 = blockIdx.y*BY;
  int HW = H*W;
  __shared__ float te[3][BY+2][BX+2];
  __shared__ float tr[3][BY+2][BX+2];
  __shared__ unsigned sh[256];
  int tid = threadIdx.y*BX + threadIdx.x;
  sh[tid] = 0u;
  for (int p=0;p<3;p++){
    int dd = l-1+p;
    bool pv = (dd>=0 && dd<=4);
    const float* ep = pv ? &g_e[dd][b*HW] : 0;
    const float* rp = pv ? &g_resp[dd][b*HW] : 0;
    for (int j = threadIdx.y; j < BY+2; j += BY){
      int gy = y0 - 1 + j;
      for (int i = threadIdx.x; i < BX+2; i += BX){
        int gx = x0 - 1 + i;
        bool ok = pv && gy>=0 && gy<H && gx>=0 && gx<W;
        te[p][j][i] = ok ? ep[gy*W+gx] : 0.f;
        tr[p][j][i] = ok ? rp[gy*W+gx] : 0.f;
      }
    }
  }
  __syncthreads();
  int x = x0 + threadIdx.x, y = y0 + threadIdx.y;
  if (x < W && y < H){
    float den=0.f, num=0.f;
    #pragma unroll
    for (int p=0;p<3;p++)
      #pragma unroll
      for (int j=0;j<3;j++)
        #pragma unroll
        for (int i=0;i<3;i++){
          float ev = te[p][threadIdx.y+j][threadIdx.x+i];
          den = __fadd_rn(den, ev);
          num = __fadd_rn(num, __fmul_rn(ev, tr[p][threadIdx.y+j][threadIdx.x+i]));
        }
    float v = __fdiv_rn(num, __fadd_rn(den, EPSF));
    g_vals[l][b*HW + y*W + x] = v;
    atomicAdd(&sh[fkey(v)>>24], 1u);
  }
  __syncthreads();
  if (sh[tid]) atomicAdd(&g_bins[b][tid], sh[tid]);
}

// ---------------- top-k machinery ----------------
// compact all elements whose top byte >= dsel0 (self-computed round-0 scan)
__global__ void k_compact1(int N,int HW){
  int b = blockIdx.y;
  __shared__ unsigned sdsel;
  if (threadIdx.x == 0){
    unsigned k = NFEAT, cum = 0; unsigned dsel = 0;
    for (int d=255; d>=0; d--){
      unsigned c = g_bins[b][d];
      if (cum + c >= k){ dsel = (unsigned)d; break; }
      cum += c;
    }
    sdsel = dsel;
  }
  __syncthreads();
  unsigned dsel = sdsel;
  for (int i=blockIdx.x*blockDim.x+threadIdx.x; i<N; i+=gridDim.x*blockDim.x){
    unsigned key = fkey(cand_val(0,b,(unsigned)i,HW));
    if ((key>>24) >= dsel){
      unsigned p = atomicAdd(&g_cnt1[b], 1u);
      if (p < C1CAP) g_cand1[b][p] = (unsigned)i;
    }
  }
}

// fused radix rounds 1..3 + final compact; resets g_bins/g_cnt1 for next octave
__global__ void k_tail(int HW){
  int b = blockIdx.x;
  __shared__ unsigned bins[256];
  __shared__ unsigned spref, skrem, scnt;
  int tid = threadIdx.x;                 // 1024 threads
  unsigned M = g_cnt1[b]; if (M > C1CAP) M = C1CAP;
  if (tid == 0){
    unsigned k = NFEAT, cum = 0; unsigned dsel = 0;
    for (int d=255; d>=0; d--){
      unsigned c = g_bins[b][d];
      if (cum + c >= k){ dsel = (unsigned)d; break; }
      cum += c;
    }
    spref = dsel; skrem = k - cum;
  }
  __syncthreads();
  for (int r=1;r<4;r++){
    if (tid < 256) bins[tid] = 0u;
    __syncthreads();
    unsigned pref = spref;
    int shift = 24 - 8*r;
    for (unsigned i=tid; i<M; i+=1024){
      unsigned key = fkey(cand_val(0,b,g_cand1[b][i],HW));
      if ((key >> (8*(4-r))) == pref) atomicAdd(&bins[(key>>shift)&0xFFu], 1u);
    }
    __syncthreads();
    if (tid == 0){
      unsigned k = skrem, cum = 0; unsigned dsel = 0;
      for (int d=255; d>=0; d--){
        unsigned c = bins[d];
        if (cum + c >= k){ dsel = (unsigned)d; break; }
        cum += c;
      }
      spref = (spref<<8) | dsel; skrem = k - cum;
      if (r == 3) scnt = 0u;
    }
    __syncthreads();
  }
  unsigned T = spref;
  for (unsigned i=tid; i<M; i+=1024){
    unsigned idx = g_cand1[b][i];
    unsigned key = fkey(cand_val(0,b,idx,HW));
    if (key >= T){
      unsigned p = atomicAdd(&scnt, 1u);
      if (p < CANDCAP) g_candlist[b][p] = idx;
    }
  }
  __syncthreads();
  if (tid < 256) g_bins[b][tid] = 0u;    // reset for next octave / next replay
  if (tid == 0){ g_candcnt[b] = scnt; g_cnt1[b] = 0u; }
}

// final selection over g_cand_resp; also sweeps octave-6 hist leftovers
__global__ void k_tailf(int N){
  int b = blockIdx.x;
  __shared__ unsigned bins[256];
  __shared__ unsigned spref, skrem, scnt;
  int tid = threadIdx.x;                 // 1024
  if (tid == 0){ spref = 0u; skrem = NFEAT; }
  __syncthreads();
  for (int r=0;r<4;r++){
    if (tid < 256) bins[tid] = 0u;
    __syncthreads();
    unsigned pref = spref;
    int shift = 24 - 8*r;
    for (int i=tid; i<N; i+=1024){
      unsigned key = fkey(g_cand_resp[b][i]);
      bool ok = (r==0) || ((key >> (8*(4-r))) == pref);
      if (ok) atomicAdd(&bins[(key>>shift)&0xFFu], 1u);
    }
    __syncthreads();
    if (tid == 0){
      unsigned k = skrem, cum = 0; unsigned dsel = 0;
      for (int d=255; d>=0; d--){
        unsigned c = bins[d];
        if (cum + c >= k){ dsel = (unsigned)d; break; }
        cum += c;
      }
      spref = (spref<<8) | dsel; skrem = k - cum;
      if (r == 3) scnt = 0u;
    }
    __syncthreads();
  }
  unsigned T = spref;
  for (int i=tid; i<N; i+=1024){
    unsigned key = fkey(g_cand_resp[b][i]);
    if (key >= T){
      unsigned p = atomicAdd(&scnt, 1u);
      if (p < CANDCAP) g_candlist[b][p] = (unsigned)i;
    }
  }
  __syncthreads();
  if (tid < 256) g_bins[b][tid] = 0u;    // sweep octave-6 fused-hist leftovers
  if (tid == 0){ g_candcnt[b] = scnt; g_cnt1[b] = 0u; }
}

__global__ void k_sortsel(int mode,int HW,int outmode){
  __shared__ unsigned long long s[SORTN];
  int b = blockIdx.x;
  unsigned M = g_candcnt[b]; if (M > CANDCAP) M = CANDCAP;
  for (int t=threadIdx.x; t<SORTN; t+=blockDim.x){
    unsigned long long kv = 0ULL;
    if (t < (int)M){
      unsigned i = g_candlist[b][t];
      kv = ((unsigned long long)fkey(cand_val(mode,b,i,HW)) << 32) | (unsigned)(~i);
    }
    s[t] = kv;
  }
  __syncthreads();
  for (int k=2; k<=SORTN; k<<=1){
    for (int j=k>>1; j>0; j>>=1){
      for (int i=threadIdx.x; i<SORTN; i+=blockDim.x){
        int p = i ^ j;
        if (p > i){
          unsigned long long a=s[i], c=s[p];
          bool up = ((i & k) == 0);
          if (up ? (a < c) : (a > c)){ s[i]=c; s[p]=a; }
        }
      }
      __syncthreads();
    }
  }
  for (int t=threadIdx.x; t<NFEAT; t+=blockDim.x){
    unsigned i = ~((unsigned)(s[t] & 0xFFFFFFFFULL));
    float v = cand_val(mode,b,i,HW);
    if (outmode==0){ g_selidx[b][t]=i; g_selval[b][t]=v; }
    else           { g_finidx[b][t]=i; g_finval[b][t]=v; }
  }
}

__global__ void k_laf(int H,int W,int count,int use_sel,int base){
  int j = blockIdx.x*blockDim.x + threadIdx.x;
  int b = blockIdx.y;
  if (j >= count) return;
  int HW = H*W;
  unsigned idx; float v;
  if (use_sel){ idx = g_selidx[b][j]; v = g_selval[b][j]; }
  else {
    idx = (unsigned)j;
    unsigned d0 = idx/(unsigned)HW;
    v = g_vals[d0][(unsigned)b*HW + (idx - d0*(unsigned)HW)];
  }
  int d = idx/HW, rem = idx-d*HW;
  int y = rem/W, x = rem-(rem/W)*W;
  float den=0.f, sd=0.f, sx=0.f, sy=0.f;
  for (int dd=d-1; dd<=d+1; dd++){
    if (dd<0 || dd>4) continue;
    const float* e = &g_e[dd][b*HW];
    for (int yy=y-1; yy<=y+1; yy++){
      if ((unsigned)yy >= (unsigned)H) continue;
      for (int xx=x-1; xx<=x+1; xx++){
        if ((unsigned)xx >= (unsigned)W) continue;
        float ev = e[yy*W+xx];
        den = __fadd_rn(den, ev);
        if (dd != d) sd = __fadd_rn(sd, __fmul_rn(ev, (float)(dd-d)));
        if (xx != x) sx = __fadd_rn(sx, __fmul_rn(ev, (float)(xx-x)));
        if (yy != y) sy = __fadd_rn(sy, __fmul_rn(ev, (float)(yy-y)));
      }
    }
  }
  float dE = __fadd_rn(den, EPSF);
  float cd = __fadd_rn(__fdiv_rn(sd,dE), (float)d);
  float cx = __fadd_rn(__fdiv_rn(sx,dE), (float)x);
  float cy = __fadd_rn(__fdiv_rn(sy,dE), (float)y);
  float scale = __fmul_rn(1.6f, (float)exp2((double)__fdiv_rn(cd, 3.0f)));
  float s6 = __fmul_rn(6.0f, scale);
  float g = ((__fsub_rn(cx,s6) > 0.f) && (__fadd_rn(cx,s6) < (float)(W-1)) &&
             (__fsub_rn(cy,s6) > 0.f) && (__fadd_rn(cy,s6) < (float)(H-1))) ? 1.f : 0.f;
  float mn = (float)(H < W ? H : W);
  int o = base + j;
  g_cand_resp[b][o] = __fmul_rn(v, g);
  float* Lf = g_cand_laf[b][o];
  Lf[0] = __fdiv_rn(s6,mn); Lf[1] = 0.f; Lf[2] = __fdiv_rn(cx,(float)W);
  Lf[3] = 0.f;              Lf[4] = __fdiv_rn(s6,mn); Lf[5] = __fdiv_rn(cy,(float)H);
}

__global__ void k_out(float* __restrict__ out){
  int t = blockIdx.x*blockDim.x + threadIdx.x;
  if (t >= 2*NFEAT) return;
  int b = t/NFEAT, j = t-b*NFEAT;
  unsigned i = g_finidx[b][j];
  const float* L = g_cand_laf[b][i];
  float* o = out + (b*NFEAT + j)*6;
  #pragma unroll
  for (int e=0;e<6;e++) o[e] = __fmul_rn(L[e], 1024.0f);
  out[2*NFEAT*6 + b*NFEAT + j] = g_finval[b][j];
}

// ---------------- host ----------------
static void launch_blur(const float* src, float* dst, int S, const KW& kw, int n){
  dim3 g((S+BX-1)/BX, (S+BYO-1)/BYO, 2);
  dim3 tb(BX, BY);
  switch(n){
    case 9:  k_blur2<9 ><<<g,tb>>>(src,dst,S,S,kw); break;
    case 11: k_blur2<11><<<g,tb>>>(src,dst,S,S,kw); break;
    case 13: k_blur2<13><<<g,tb>>>(src,dst,S,S,kw); break;
    case 15: k_blur2<15><<<g,tb>>>(src,dst,S,S,kw); break;
    case 17: k_blur2<17><<<g,tb>>>(src,dst,S,S,kw); break;
    case 19: k_blur2<19><<<g,tb>>>(src,dst,S,S,kw); break;
    default: k_blur2<21><<<g,tb>>>(src,dst,S,S,kw); break;
  }
}

extern "C" void kernel_launch(void* const* d_in, const int* in_sizes, int n_in,
                              void* d_out, int out_size){
  (void)in_sizes; (void)n_in; (void)out_size;
  const float* img = (const float*)d_in[0];
  float* out = (float*)d_out;

  float *p_lv = 0;
  cudaGetSymbolAddress((void**)&p_lv, g_lv);

  double step = pow(2.0, 1.0/3.0);
  double q = sqrt(step*step - 1.0);
  double sgm[5]; int ksz[5];
  sgm[0] = sqrt(1.6*1.6 - 0.25);
  { double cs = 1.6; for (int i=1;i<5;i++){ sgm[i] = cs * q; cs *= step; } }
  for (int i=0;i<5;i++){ int k=(int)(8.0*sgm[i]+1.0); if(!(k&1))k++; ksz[i]=k; }
  float s4[5];
  { double cs = 1.6;
    for (int l=0;l<5;l++){ float sgf=(float)cs; s4[l]=powf(sgf,4.0f); cs*=step; } }

  // host weight pipeline: identical f32 op sequence (volatile blocks reassociation)
  KW kws[5];
  for (int t=0;t<5;t++){
    int n = ksz[t], h = n/2;
    volatile float den2 = (float)(2.0*sgm[t]*sgm[t]);
    float w[32];
    for (int i=0;i<n;i++){
      volatile float x = (float)(i - h);
      volatile float arg = -(x*x)/den2;
      w[i] = (float)exp((double)arg);
    }
    volatile float r[8];
    for (int j=0;j<8;j++) r[j] = w[j];
    int i = 8;
    for (; i + 8 <= n; i += 8)
      for (int j=0;j<8;j++) r[j] = r[j] + w[i+j];
    volatile float s01 = r[0]+r[1], s23 = r[2]+r[3], s45 = r[4]+r[5], s67 = r[6]+r[7];
    volatile float s0123 = s01+s23, s4567 = s45+s67;
    volatile float sum = s0123 + s4567;
    for (; i < n; i++) sum = sum + w[i];
    for (int k2=0;k2<24;k2++) kws[t].w[k2] = 0.f;
    for (int k2=0;k2<n;k2++) kws[t].w[k2] = w[k2]/sum;
  }

  static const int SS[7] = {1024,512,256,128,64,32,16};
  int base = 0;
  for (int o=0;o<7;o++){
    int S = SS[o], HW = S*S, tot = 2*HW;
    if (o == 0){
      launch_blur(img, p_lv, S, kws[0], ksz[0]);
    } else {
      int thr = 256, blk = (tot+thr-1)/thr;
      k_down<<<blk,thr>>>(S);
    }
    for (int i=1;i<5;i++)
      launch_blur(p_lv+(i-1)*LVS, p_lv+i*LVS, S, kws[i], ksz[i]);

    dim3 tg((S+BX-1)/BX, (S+BY-1)/BY, 10);
    dim3 tb(BX, BY);
    k_hess2<<<tg,tb>>>(S,S,s4[0],s4[1],s4[2],s4[3],s4[4]);
    k_emap2<<<tg,tb>>>(S,S);
    k_vals2<<<tg,tb>>>(S,S);

    int N = 5*HW;
    if (N > NFEAT){
      int hb = (N+255)/256; if (hb > 2048) hb = 2048;
      k_compact1<<<dim3(hb,2),256>>>(N,HW);     // self round-0 scan + compact
      k_tail<<<2,1024>>>(HW);                   // rounds 1-3 + compact + reset
      k_sortsel<<<2,512>>>(0,HW,0);
      k_laf<<<dim3((NFEAT+127)/128,2),128>>>(S,S,NFEAT,1,base);
      base += NFEAT;
    } else {
      k_laf<<<dim3((N+127)/128,2),128>>>(S,S,N,0,base);
      base += N;
    }
  }

  // final selection over all candidates (base == 13280), fully fused
  k_tailf<<<2,1024>>>(base);
  k_sortsel<<<2,512>>>(1,0,1);
  k_out<<<(2*NFEAT+255)/256,256>>>(out);
}

// round 16
// speedup vs baseline: 1.0171x; 1.0171x over previous
#include <cuda_runtime.h>
#include <math.h>

#define NFEAT   2000
#define TOTCAND 13280
#define MAXHW   (1024*1024)
#define LVS     (2*MAXHW)
#define EPSF    1e-8f
#define CANDCAP 4096
#define SORTN   4096
#define C1CAP   262144
#define BX 32
#define BY 8

// ---------------- static device scratch ----------------
__device__ float g_lv[5][LVS];
__device__ float g_resp[5][LVS];
__device__ float g_e[5][LVS];
__device__ float g_vals[5][LVS];

__device__ unsigned g_bins[2][256];
__device__ unsigned g_candcnt[2];
__device__ unsigned g_cnt1[2];
__device__ unsigned g_cand1[2][C1CAP];
__device__ unsigned g_candlist[2][CANDCAP];
__device__ unsigned g_selidx[2][NFEAT];
__device__ float    g_selval[2][NFEAT];
__device__ float    g_cand_resp[2][TOTCAND];
__device__ float    g_cand_laf[2][TOTCAND][6];
__device__ unsigned g_finidx[2][NFEAT];
__device__ float    g_finval[2][NFEAT];

struct KW { float w[24]; };   // blur weights passed by value (const bank)

// Hessian kernels (reference _K2 / abs-sum: /64, /36, /64; f32-exact constants)
__constant__ float cGXX[25] = {
 -1.f/64,0.f,2.f/64,0.f,-1.f/64, -4.f/64,0.f,8.f/64,0.f,-4.f/64,
 -6.f/64,0.f,12.f/64,0.f,-6.f/64, -4.f/64,0.f,8.f/64,0.f,-4.f/64,
 -1.f/64,0.f,2.f/64,0.f,-1.f/64 };
__constant__ float cGXY[25] = {
 (float)(-1.0/36),(float)(-2.0/36),0.f,(float)(2.0/36),(float)(1.0/36),
 (float)(-2.0/36),(float)(-4.0/36),0.f,(float)(4.0/36),(float)(2.0/36),
 0.f,0.f,0.f,0.f,0.f,
 (float)(2.0/36),(float)(4.0/36),0.f,(float)(-4.0/36),(float)(-2.0/36),
 (float)(1.0/36),(float)(2.0/36),0.f,(float)(-2.0/36),(float)(-1.0/36) };
__constant__ float cGYY[25] = {     // _GXX.T
 -1.f/64,-4.f/64,-6.f/64,-4.f/64,-1.f/64, 0.f,0.f,0.f,0.f,0.f,
 2.f/64,8.f/64,12.f/64,8.f/64,2.f/64, 0.f,0.f,0.f,0.f,0.f,
 -1.f/64,-4.f/64,-6.f/64,-4.f/64,-1.f/64 };

// XLA-CPU inline exp (Cephes), every mul/add UNFUSED — bit-exact
__device__ __forceinline__ float xla_expf(float input){
  float x = fminf(input, 88.3762626647950f);
  x = fmaxf(x, -88.3762626647949f);
  float fx = floorf(__fadd_rn(__fmul_rn(x, 1.44269504088896341f), 0.5f));
  float tmp = __fmul_rn(fx, 0.693359375f);
  float z   = __fmul_rn(fx, -2.12194440e-4f);
  x = __fsub_rn(x, tmp);
  x = __fsub_rn(x, z);
  float z2 = __fmul_rn(x, x);
  float y = 1.9875691500E-4f;
  y = __fadd_rn(__fmul_rn(y, x), 1.3981999507E-3f);
  y = __fadd_rn(__fmul_rn(y, x), 8.3334519073E-3f);
  y = __fadd_rn(__fmul_rn(y, x), 4.1665795894E-2f);
  y = __fadd_rn(__fmul_rn(y, x), 1.6666665459E-1f);
  y = __fadd_rn(__fmul_rn(y, x), 5.0000001201E-1f);
  y = __fadd_rn(__fmul_rn(y, z2), x);
  y = __fadd_rn(y, 1.0f);
  int n = (int)fx;
  float p2n = __uint_as_float((unsigned)(n + 127) << 23);
  return __fmul_rn(y, p2n);
}

__device__ __forceinline__ unsigned fkey(float f){
  unsigned u = __float_as_uint(f);
  if ((u << 1) == 0u) return 0x80000000u;
  return (u & 0x80000000u) ? ~u : (u | 0x80000000u);
}

__device__ __forceinline__ float cand_val(int mode, int b, unsigned i, int HW){
  if (mode == 0){
    unsigned d = i / (unsigned)HW;
    return g_vals[d][(unsigned)b*HW + (i - d*(unsigned)HW)];
  }
  return g_cand_resp[b][i];
}

// ---------------- fused separable blur, wide tile ----------------
// Tile 128 x 8 per 32x8 block. Vertical pass: each thread ~4.6 columns of its
// row (unrolled, independent chains). Horizontal: 4 outputs/thread at stride 32
// (conflict-free smem, 4 independent chains). Per-output tap order identical to
// the two-pass reference: bit-exact.
template<int N>
__global__ void k_blur3(const float* __restrict__ src, float* __restrict__ dst,
                        int H,int W, KW kw){
  const int P = N/2;
  const int TILE = 128;
  const int NCOLS = TILE + 2*P;
  const int KMAX = (NCOLS + 31)/32;
  int x0 = blockIdx.x*TILE, y0 = blockIdx.y*8, b = blockIdx.z;
  const float* s = src + (size_t)b*H*W;
  __shared__ float sv[8][TILE + 2*10 + 4];
  int y = y0 + threadIdx.y;
  if (y < H){
    bool interior = (y >= P && y + P < H);
    #pragma unroll
    for (int k=0;k<KMAX;k++){
      int cc = threadIdx.x + 32*k;
      if (cc >= NCOLS) break;
      int gx = x0 + cc - P;
      if (gx >= W + P) continue;            // never read; reflection invalid
      gx = (gx<0) ? -gx : ((gx>=W) ? (2*W-2-gx) : gx);
      float acc = 0.f;
      if (interior){
        #pragma unroll
        for (int i=0;i<N;i++)
          acc = __fadd_rn(acc, __fmul_rn(kw.w[i], s[(y+i-P)*W + gx]));
      } else {
        #pragma unroll
        for (int i=0;i<N;i++){
          int t = y+i-P;
          t = (t<0) ? -t : ((t>=H) ? (2*H-2-t) : t);
          acc = __fadd_rn(acc, __fmul_rn(kw.w[i], s[t*W + gx]));
        }
      }
      sv[threadIdx.y][cc] = acc;
    }
  }
  __syncthreads();
  if (y >= H) return;
  float* drow = dst + (size_t)b*H*W + y*W;
  #pragma unroll
  for (int j=0;j<4;j++){
    int xo = threadIdx.x + 32*j;
    int x = x0 + xo;
    if (x >= W) continue;
    float acc = 0.f;
    #pragma unroll
    for (int i=0;i<N;i++)
      acc = __fadd_rn(acc, __fmul_rn(kw.w[i], sv[threadIdx.y][xo + i]));
    drow[x] = acc;
  }
}

__global__ void k_down(int S){
  int idx = blockIdx.x*blockDim.x + threadIdx.x;
  int HW = S*S, tot = 2*HW; if (idx >= tot) return;
  int b = idx/HW, rem = idx-b*HW;
  int y = rem/S, x = rem-(rem/S)*S;
  int S2 = 2*S, HW2 = 4*HW;
  g_lv[0][idx] = g_lv[3][b*HW2 + (2*y)*S2 + 2*x];
}

// ---------------- hessian: smem-tiled, kh outer / kw inner, UNFUSED ----------------
__global__ void k_hess2(int H,int W,float q0,float q1,float q2,float q3,float q4){
  int l = blockIdx.z % 5, b = blockIdx.z / 5;
  int x0 = blockIdx.x*BX, y0 = blockIdx.y*BY;
  __shared__ float t[BY+4][BX+4];
  const float* s = &g_lv[l][b*H*W];
  for (int j = threadIdx.y; j < BY+4; j += BY){
    int yy = y0 + j - 2; yy = yy<0?0:(yy>H-1?H-1:yy);
    for (int i = threadIdx.x; i < BX+4; i += BX){
      int xx = x0 + i - 2; xx = xx<0?0:(xx>W-1?W-1:xx);
      t[j][i] = s[yy*W+xx];
    }
  }
  __syncthreads();
  int x = x0 + threadIdx.x, y = y0 + threadIdx.y;
  if (x >= W || y >= H) return;
  float dxx=0.f,dxy=0.f,dyy=0.f;
  #pragma unroll
  for (int i=0;i<5;i++){
    #pragma unroll
    for (int j=0;j<5;j++){
      float pv = t[threadIdx.y+i][threadIdx.x+j];
      dxx = __fadd_rn(dxx, __fmul_rn(cGXX[i*5+j], pv));
      dxy = __fadd_rn(dxy, __fmul_rn(cGXY[i*5+j], pv));
      dyy = __fadd_rn(dyy, __fmul_rn(cGYY[i*5+j], pv));
    }
  }
  float s4 = (l==0)?q0:(l==1)?q1:(l==2)?q2:(l==3)?q3:q4;
  float det = __fsub_rn(__fmul_rn(dxx,dyy), __fmul_rn(dxy,dxy));
  g_resp[l][(size_t)b*H*W + y*W + x] = __fmul_rn(det, s4);
}

// ---------------- emap: tiled 3 planes, -FLT_MAX pad (max exact) ----------------
__global__ void k_emap2(int H,int W){
  int l = blockIdx.z % 5, b = blockIdx.z / 5;
  int x0 = blockIdx.x*BX, y0 = blockIdx.y*BY;
  int HW = H*W;
  __shared__ float t[3][BY+2][BX+2];
  for (int p=0;p<3;p++){
    int dd = l-1+p;
    bool pv = (dd>=0 && dd<=4);
    const float* rp = pv ? &g_resp[dd][b*HW] : 0;
    for (int j = threadIdx.y; j < BY+2; j += BY){
      int gy = y0 - 1 + j;
      for (int i = threadIdx.x; i < BX+2; i += BX){
        int gx = x0 - 1 + i;
        bool ok = pv && gy>=0 && gy<H && gx>=0 && gx<W;
        t[p][j][i] = ok ? rp[gy*W+gx] : -3.402823466e38f;
      }
    }
  }
  __syncthreads();
  int x = x0 + threadIdx.x, y = y0 + threadIdx.y;
  if (x >= W || y >= H) return;
  float m = -3.402823466e38f;
  #pragma unroll
  for (int p=0;p<3;p++)
    #pragma unroll
    for (int j=0;j<3;j++)
      #pragma unroll
      for (int i=0;i<3;i++)
        m = fmaxf(m, t[p][threadIdx.y+j][threadIdx.x+i]);
  float c = t[1][threadIdx.y+1][threadIdx.x+1];
  g_e[l][b*HW + y*W + x] = xla_expf(__fsub_rn(c, m));
}

// ---------------- vals: tiled, +0 pad (exact no-op), fused round-0 hist ----------
__global__ void k_vals2(int H,int W){
  int l = blockIdx.z % 5, b = blockIdx.z / 5;
  int x0 = blockIdx.x*BX, y0 = blockIdx.y*BY;
  int HW = H*W;
  __shared__ float te[3][BY+2][BX+2];
  __shared__ float tr[3][BY+2][BX+2];
  __shared__ unsigned sh[256];
  int tid = threadIdx.y*BX + threadIdx.x;
  sh[tid] = 0u;
  for (int p=0;p<3;p++){
    int dd = l-1+p;
    bool pv = (dd>=0 && dd<=4);
    const float* ep = pv ? &g_e[dd][b*HW] : 0;
    const float* rp = pv ? &g_resp[dd][b*HW] : 0;
    for (int j = threadIdx.y; j < BY+2; j += BY){
      int gy = y0 - 1 + j;
      for (int i = threadIdx.x; i < BX+2; i += BX){
        int gx = x0 - 1 + i;
        bool ok = pv && gy>=0 && gy<H && gx>=0 && gx<W;
        te[p][j][i] = ok ? ep[gy*W+gx] : 0.f;
        tr[p][j][i] = ok ? rp[gy*W+gx] : 0.f;
      }
    }
  }
  __syncthreads();
  int x = x0 + threadIdx.x, y = y0 + threadIdx.y;
  if (x < W && y < H){
    float den=0.f, num=0.f;
    #pragma unroll
    for (int p=0;p<3;p++)
      #pragma unroll
      for (int j=0;j<3;j++)
        #pragma unroll
        for (int i=0;i<3;i++){
          float ev = te[p][threadIdx.y+j][threadIdx.x+i];
          den = __fadd_rn(den, ev);
          num = __fadd_rn(num, __fmul_rn(ev, tr[p][threadIdx.y+j][threadIdx.x+i]));
        }
    float v = __fdiv_rn(num, __fadd_rn(den, EPSF));
    g_vals[l][b*HW + y*W + x] = v;
    atomicAdd(&sh[fkey(v)>>24], 1u);
  }
  __syncthreads();
  if (sh[tid]) atomicAdd(&g_bins[b][tid], sh[tid]);
}

// ---------------- top-k machinery ----------------
__global__ void k_compact1(int N,int HW){
  int b = blockIdx.y;
  __shared__ unsigned sdsel;
  if (threadIdx.x == 0){
    unsigned k = NFEAT, cum = 0; unsigned dsel = 0;
    for (int d=255; d>=0; d--){
      unsigned c = g_bins[b][d];
      if (cum + c >= k){ dsel = (unsigned)d; break; }
      cum += c;
    }
    sdsel = dsel;
  }
  __syncthreads();
  unsigned dsel = sdsel;
  for (int i=blockIdx.x*blockDim.x+threadIdx.x; i<N; i+=gridDim.x*blockDim.x){
    unsigned key = fkey(cand_val(0,b,(unsigned)i,HW));
    if ((key>>24) >= dsel){
      unsigned p = atomicAdd(&g_cnt1[b], 1u);
      if (p < C1CAP) g_cand1[b][p] = (unsigned)i;
    }
  }
}

__global__ void k_tail(int HW){
  int b = blockIdx.x;
  __shared__ unsigned bins[256];
  __shared__ unsigned spref, skrem, scnt;
  int tid = threadIdx.x;                 // 1024 threads
  unsigned M = g_cnt1[b]; if (M > C1CAP) M = C1CAP;
  if (tid == 0){
    unsigned k = NFEAT, cum = 0; unsigned dsel = 0;
    for (int d=255; d>=0; d--){
      unsigned c = g_bins[b][d];
      if (cum + c >= k){ dsel = (unsigned)d; break; }
      cum += c;
    }
    spref = dsel; skrem = k - cum;
  }
  __syncthreads();
  for (int r=1;r<4;r++){
    if (tid < 256) bins[tid] = 0u;
    __syncthreads();
    unsigned pref = spref;
    int shift = 24 - 8*r;
    for (unsigned i=tid; i<M; i+=1024){
      unsigned key = fkey(cand_val(0,b,g_cand1[b][i],HW));
      if ((key >> (8*(4-r))) == pref) atomicAdd(&bins[(key>>shift)&0xFFu], 1u);
    }
    __syncthreads();
    if (tid == 0){
      unsigned k = skrem, cum = 0; unsigned dsel = 0;
      for (int d=255; d>=0; d--){
        unsigned c = bins[d];
        if (cum + c >= k){ dsel = (unsigned)d; break; }
        cum += c;
      }
      spref = (spref<<8) | dsel; skrem = k - cum;
      if (r == 3) scnt = 0u;
    }
    __syncthreads();
  }
  unsigned T = spref;
  for (unsigned i=tid; i<M; i+=1024){
    unsigned idx = g_cand1[b][i];
    unsigned key = fkey(cand_val(0,b,idx,HW));
    if (key >= T){
      unsigned p = atomicAdd(&scnt, 1u);
      if (p < CANDCAP) g_candlist[b][p] = idx;
    }
  }
  __syncthreads();
  if (tid < 256) g_bins[b][tid] = 0u;    // reset for next octave / next replay
  if (tid == 0){ g_candcnt[b] = scnt; g_cnt1[b] = 0u; }
}

__global__ void k_tailf(int N){
  int b = blockIdx.x;
  __shared__ unsigned bins[256];
  __shared__ unsigned spref, skrem, scnt;
  int tid = threadIdx.x;                 // 1024
  if (tid == 0){ spref = 0u; skrem = NFEAT; }
  __syncthreads();
  for (int r=0;r<4;r++){
    if (tid < 256) bins[tid] = 0u;
    __syncthreads();
    unsigned pref = spref;
    int shift = 24 - 8*r;
    for (int i=tid; i<N; i+=1024){
      unsigned key = fkey(g_cand_resp[b][i]);
      bool ok = (r==0) || ((key >> (8*(4-r))) == pref);
      if (ok) atomicAdd(&bins[(key>>shift)&0xFFu], 1u);
    }
    __syncthreads();
    if (tid == 0){
      unsigned k = skrem, cum = 0; unsigned dsel = 0;
      for (int d=255; d>=0; d--){
        unsigned c = bins[d];
        if (cum + c >= k){ dsel = (unsigned)d; break; }
        cum += c;
      }
      spref = (spref<<8) | dsel; skrem = k - cum;
      if (r == 3) scnt = 0u;
    }
    __syncthreads();
  }
  unsigned T = spref;
  for (int i=tid; i<N; i+=1024){
    unsigned key = fkey(g_cand_resp[b][i]);
    if (key >= T){
      unsigned p = atomicAdd(&scnt, 1u);
      if (p < CANDCAP) g_candlist[b][p] = (unsigned)i;
    }
  }
  __syncthreads();
  if (tid < 256) g_bins[b][tid] = 0u;
  if (tid == 0){ g_candcnt[b] = scnt; g_cnt1[b] = 0u; }
}

__global__ void k_sortsel(int mode,int HW,int outmode){
  __shared__ unsigned long long s[SORTN];
  int b = blockIdx.x;
  unsigned M = g_candcnt[b]; if (M > CANDCAP) M = CANDCAP;
  for (int t=threadIdx.x; t<SORTN; t+=blockDim.x){
    unsigned long long kv = 0ULL;
    if (t < (int)M){
      unsigned i = g_candlist[b][t];
      kv = ((unsigned long long)fkey(cand_val(mode,b,i,HW)) << 32) | (unsigned)(~i);
    }
    s[t] = kv;
  }
  __syncthreads();
  for (int k=2; k<=SORTN; k<<=1){
    for (int j=k>>1; j>0; j>>=1){
      for (int i=threadIdx.x; i<SORTN; i+=blockDim.x){
        int p = i ^ j;
        if (p > i){
          unsigned long long a=s[i], c=s[p];
          bool up = ((i & k) == 0);
          if (up ? (a < c) : (a > c)){ s[i]=c; s[p]=a; }
        }
      }
      __syncthreads();
    }
  }
  for (int t=threadIdx.x; t<NFEAT; t+=blockDim.x){
    unsigned i = ~((unsigned)(s[t] & 0xFFFFFFFFULL));
    float v = cand_val(mode,b,i,HW);
    if (outmode==0){ g_selidx[b][t]=i; g_selval[b][t]=v; }
    else           { g_finidx[b][t]=i; g_finval[b][t]=v; }
  }
}

__global__ void k_laf(int H,int W,int count,int use_sel,int base){
  int j = blockIdx.x*blockDim.x + threadIdx.x;
  int b = blockIdx.y;
  if (j >= count) return;
  int HW = H*W;
  unsigned idx; float v;
  if (use_sel){ idx = g_selidx[b][j]; v = g_selval[b][j]; }
  else {
    idx = (unsigned)j;
    unsigned d0 = idx/(unsigned)HW;
    v = g_vals[d0][(unsigned)b*HW + (idx - d0*(unsigned)HW)];
  }
  int d = idx/HW, rem = idx-d*HW;
  int y = rem/W, x = rem-(rem/W)*W;
  float den=0.f, sd=0.f, sx=0.f, sy=0.f;
  for (int dd=d-1; dd<=d+1; dd++){
    if (dd<0 || dd>4) continue;
    const float* e = &g_e[dd][b*HW];
    for (int yy=y-1; yy<=y+1; yy++){
      if ((unsigned)yy >= (unsigned)H) continue;
      for (int xx=x-1; xx<=x+1; xx++){
        if ((unsigned)xx >= (unsigned)W) continue;
        float ev = e[yy*W+xx];
        den = __fadd_rn(den, ev);
        if (dd != d) sd = __fadd_rn(sd, __fmul_rn(ev, (float)(dd-d)));
        if (xx != x) sx = __fadd_rn(sx, __fmul_rn(ev, (float)(xx-x)));
        if (yy != y) sy = __fadd_rn(sy, __fmul_rn(ev, (float)(yy-y)));
      }
    }
  }
  float dE = __fadd_rn(den, EPSF);
  float cd = __fadd_rn(__fdiv_rn(sd,dE), (float)d);
  float cx = __fadd_rn(__fdiv_rn(sx,dE), (float)x);
  float cy = __fadd_rn(__fdiv_rn(sy,dE), (float)y);
  float scale = __fmul_rn(1.6f, (float)exp2((double)__fdiv_rn(cd, 3.0f)));
  float s6 = __fmul_rn(6.0f, scale);
  float g = ((__fsub_rn(cx,s6) > 0.f) && (__fadd_rn(cx,s6) < (float)(W-1)) &&
             (__fsub_rn(cy,s6) > 0.f) && (__fadd_rn(cy,s6) < (float)(H-1))) ? 1.f : 0.f;
  float mn = (float)(H < W ? H : W);
  int o = base + j;
  g_cand_resp[b][o] = __fmul_rn(v, g);
  float* Lf = g_cand_laf[b][o];
  Lf[0] = __fdiv_rn(s6,mn); Lf[1] = 0.f; Lf[2] = __fdiv_rn(cx,(float)W);
  Lf[3] = 0.f;              Lf[4] = __fdiv_rn(s6,mn); Lf[5] = __fdiv_rn(cy,(float)H);
}

__global__ void k_out(float* __restrict__ out){
  int t = blockIdx.x*blockDim.x + threadIdx.x;
  if (t >= 2*NFEAT) return;
  int b = t/NFEAT, j = t-b*NFEAT;
  unsigned i = g_finidx[b][j];
  const float* L = g_cand_laf[b][i];
  float* o = out + (b*NFEAT + j)*6;
  #pragma unroll
  for (int e=0;e<6;e++) o[e] = __fmul_rn(L[e], 1024.0f);
  out[2*NFEAT*6 + b*NFEAT + j] = g_finval[b][j];
}

// ---------------- host ----------------
static void launch_blur(const float* src, float* dst, int S, const KW& kw, int n){
  dim3 g((S+127)/128, (S+7)/8, 2);
  dim3 tb(32, 8);
  switch(n){
    case 9:  k_blur3<9 ><<<g,tb>>>(src,dst,S,S,kw); break;
    case 11: k_blur3<11><<<g,tb>>>(src,dst,S,S,kw); break;
    case 13: k_blur3<13><<<g,tb>>>(src,dst,S,S,kw); break;
    case 15: k_blur3<15><<<g,tb>>>(src,dst,S,S,kw); break;
    case 17: k_blur3<17><<<g,tb>>>(src,dst,S,S,kw); break;
    case 19: k_blur3<19><<<g,tb>>>(src,dst,S,S,kw); break;
    default: k_blur3<21><<<g,tb>>>(src,dst,S,S,kw); break;
  }
}

extern "C" void kernel_launch(void* const* d_in, const int* in_sizes, int n_in,
                              void* d_out, int out_size){
  (void)in_sizes; (void)n_in; (void)out_size;
  const float* img = (const float*)d_in[0];
  float* out = (float*)d_out;

  float *p_lv = 0;
  cudaGetSymbolAddress((void**)&p_lv, g_lv);

  double step = pow(2.0, 1.0/3.0);
  double q = sqrt(step*step - 1.0);
  double sgm[5]; int ksz[5];
  sgm[0] = sqrt(1.6*1.6 - 0.25);
  { double cs = 1.6; for (int i=1;i<5;i++){ sgm[i] = cs * q; cs *= step; } }
  for (int i=0;i<5;i++){ int k=(int)(8.0*sgm[i]+1.0); if(!(k&1))k++; ksz[i]=k; }
  float s4[5];
  { double cs = 1.6;
    for (int l=0;l<5;l++){ float sgf=(float)cs; s4[l]=powf(sgf,4.0f); cs*=step; } }

  // host weight pipeline: identical f32 op sequence (volatile blocks reassociation)
  KW kws[5];
  for (int t=0;t<5;t++){
    int n = ksz[t], h = n/2;
    volatile float den2 = (float)(2.0*sgm[t]*sgm[t]);
    float w[32];
    for (int i=0;i<n;i++){
      volatile float x = (float)(i - h);
      volatile float arg = -(x*x)/den2;
      w[i] = (float)exp((double)arg);
    }
    volatile float r[8];
    for (int j=0;j<8;j++) r[j] = w[j];
    int i = 8;
    for (; i + 8 <= n; i += 8)
      for (int j=0;j<8;j++) r[j] = r[j] + w[i+j];
    volatile float s01 = r[0]+r[1], s23 = r[2]+r[3], s45 = r[4]+r[5], s67 = r[6]+r[7];
    volatile float s0123 = s01+s23, s4567 = s45+s67;
    volatile float sum = s0123 + s4567;
    for (; i < n; i++) sum = sum + w[i];
    for (int k2=0;k2<24;k2++) kws[t].w[k2] = 0.f;
    for (int k2=0;k2<n;k2++) kws[t].w[k2] = w[k2]/sum;
  }

  static const int SS[7] = {1024,512,256,128,64,32,16};
  int base = 0;
  for (int o=0;o<7;o++){
    int S = SS[o], HW = S*S, tot = 2*HW;
    if (o == 0){
      launch_blur(img, p_lv, S, kws[0], ksz[0]);
    } else {
      int thr = 256, blk = (tot+thr-1)/thr;
      k_down<<<blk,thr>>>(S);
    }
    for (int i=1;i<5;i++)
      launch_blur(p_lv+(i-1)*LVS, p_lv+i*LVS, S, kws[i], ksz[i]);

    dim3 tg((S+BX-1)/BX, (S+BY-1)/BY, 10);
    dim3 tb(BX, BY);
    k_hess2<<<tg,tb>>>(S,S,s4[0],s4[1],s4[2],s4[3],s4[4]);
    k_emap2<<<tg,tb>>>(S,S);
    k_vals2<<<tg,tb>>>(S,S);

    int N = 5*HW;
    if (N > NFEAT){
      int hb = (N+255)/256; if (hb > 2048) hb = 2048;
      k_compact1<<<dim3(hb,2),256>>>(N,HW);     // self round-0 scan + compact
      k_tail<<<2,1024>>>(HW);                   // rounds 1-3 + compact + reset
      k_sortsel<<<2,512>>>(0,HW,0);
      k_laf<<<dim3((NFEAT+127)/128,2),128>>>(S,S,NFEAT,1,base);
      base += NFEAT;
    } else {
      k_laf<<<dim3((N+127)/128,2),128>>>(S,S,N,0,base);
      base += N;
    }
  }

  // final selection over all candidates (base == 13280), fully fused
  k_tailf<<<2,1024>>>(base);
  k_sortsel<<<2,512>>>(1,0,1);
  k_out<<<(2*NFEAT+255)/256,256>>>(out);
}

// round 17
// speedup vs baseline: 1.1541x; 1.1347x over previous
#include <cuda_runtime.h>
#include <math.h>

#define NFEAT   2000
#define TOTCAND 13280
#define MAXHW   (1024*1024)
#define LVS     (2*MAXHW)
#define EPSF    1e-8f
#define CANDCAP 4096
#define SORTN   4096
#define C1CAP   262144
#define BX 32
#define BY 8

// ---------------- static device scratch ----------------
__device__ float g_lv[5][LVS];
__device__ float g_e[5][LVS];
__device__ float g_vals[5][LVS];

__device__ unsigned g_bins[2][256];
__device__ unsigned g_candcnt[2];
__device__ unsigned g_cnt1[2];
__device__ unsigned g_cand1[2][C1CAP];
__device__ unsigned g_candlist[2][CANDCAP];
__device__ unsigned g_selidx[2][NFEAT];
__device__ float    g_selval[2][NFEAT];
__device__ float    g_cand_resp[2][TOTCAND];
__device__ float    g_cand_laf[2][TOTCAND][6];
__device__ unsigned g_finidx[2][NFEAT];
__device__ float    g_finval[2][NFEAT];

struct KW { float w[24]; };   // blur weights passed by value (const bank)

// Hessian kernels (reference _K2 / abs-sum: /64, /36, /64; f32-exact constants)
__constant__ float cGXX[25] = {
 -1.f/64,0.f,2.f/64,0.f,-1.f/64, -4.f/64,0.f,8.f/64,0.f,-4.f/64,
 -6.f/64,0.f,12.f/64,0.f,-6.f/64, -4.f/64,0.f,8.f/64,0.f,-4.f/64,
 -1.f/64,0.f,2.f/64,0.f,-1.f/64 };
__constant__ float cGXY[25] = {
 (float)(-1.0/36),(float)(-2.0/36),0.f,(float)(2.0/36),(float)(1.0/36),
 (float)(-2.0/36),(float)(-4.0/36),0.f,(float)(4.0/36),(float)(2.0/36),
 0.f,0.f,0.f,0.f,0.f,
 (float)(2.0/36),(float)(4.0/36),0.f,(float)(-4.0/36),(float)(-2.0/36),
 (float)(1.0/36),(float)(2.0/36),0.f,(float)(-2.0/36),(float)(-1.0/36) };
__constant__ float cGYY[25] = {     // _GXX.T
 -1.f/64,-4.f/64,-6.f/64,-4.f/64,-1.f/64, 0.f,0.f,0.f,0.f,0.f,
 2.f/64,8.f/64,12.f/64,8.f/64,2.f/64, 0.f,0.f,0.f,0.f,0.f,
 -1.f/64,-4.f/64,-6.f/64,-4.f/64,-1.f/64 };

// XLA-CPU inline exp (Cephes), every mul/add UNFUSED — bit-exact
__device__ __forceinline__ float xla_expf(float input){
  float x = fminf(input, 88.3762626647950f);
  x = fmaxf(x, -88.3762626647949f);
  float fx = floorf(__fadd_rn(__fmul_rn(x, 1.44269504088896341f), 0.5f));
  float tmp = __fmul_rn(fx, 0.693359375f);
  float z   = __fmul_rn(fx, -2.12194440e-4f);
  x = __fsub_rn(x, tmp);
  x = __fsub_rn(x, z);
  float z2 = __fmul_rn(x, x);
  float y = 1.9875691500E-4f;
  y = __fadd_rn(__fmul_rn(y, x), 1.3981999507E-3f);
  y = __fadd_rn(__fmul_rn(y, x), 8.3334519073E-3f);
  y = __fadd_rn(__fmul_rn(y, x), 4.1665795894E-2f);
  y = __fadd_rn(__fmul_rn(y, x), 1.6666665459E-1f);
  y = __fadd_rn(__fmul_rn(y, x), 5.0000001201E-1f);
  y = __fadd_rn(__fmul_rn(y, z2), x);
  y = __fadd_rn(y, 1.0f);
  int n = (int)fx;
  float p2n = __uint_as_float((unsigned)(n + 127) << 23);
  return __fmul_rn(y, p2n);
}

__device__ __forceinline__ unsigned fkey(float f){
  unsigned u = __float_as_uint(f);
  if ((u << 1) == 0u) return 0x80000000u;
  return (u & 0x80000000u) ? ~u : (u | 0x80000000u);
}

__device__ __forceinline__ float cand_val(int mode, int b, unsigned i, int HW){
  if (mode == 0){
    unsigned d = i / (unsigned)HW;
    return g_vals[d][(unsigned)b*HW + (i - d*(unsigned)HW)];
  }
  return g_cand_resp[b][i];
}

// ---------------- fused separable blur, wide tile (R16 design, kept) ----------
template<int N>
__global__ void k_blur3(const float* __restrict__ src, float* __restrict__ dst,
                        int H,int W, KW kw){
  const int P = N/2;
  const int TILE = 128;
  const int NCOLS = TILE + 2*P;
  const int KMAX = (NCOLS + 31)/32;
  int x0 = blockIdx.x*TILE, y0 = blockIdx.y*8, b = blockIdx.z;
  const float* s = src + (size_t)b*H*W;
  __shared__ float sv[8][TILE + 2*10 + 4];
  int y = y0 + threadIdx.y;
  if (y < H){
    bool interior = (y >= P && y + P < H);
    #pragma unroll
    for (int k=0;k<KMAX;k++){
      int cc = threadIdx.x + 32*k;
      if (cc >= NCOLS) break;
      int gx = x0 + cc - P;
      if (gx >= W + P) continue;
      gx = (gx<0) ? -gx : ((gx>=W) ? (2*W-2-gx) : gx);
      float acc = 0.f;
      if (interior){
        #pragma unroll
        for (int i=0;i<N;i++)
          acc = __fadd_rn(acc, __fmul_rn(kw.w[i], s[(y+i-P)*W + gx]));
      } else {
        #pragma unroll
        for (int i=0;i<N;i++){
          int t = y+i-P;
          t = (t<0) ? -t : ((t>=H) ? (2*H-2-t) : t);
          acc = __fadd_rn(acc, __fmul_rn(kw.w[i], s[t*W + gx]));
        }
      }
      sv[threadIdx.y][cc] = acc;
    }
  }
  __syncthreads();
  if (y >= H) return;
  float* drow = dst + (size_t)b*H*W + y*W;
  #pragma unroll
  for (int j=0;j<4;j++){
    int xo = threadIdx.x + 32*j;
    int x = x0 + xo;
    if (x >= W) continue;
    float acc = 0.f;
    #pragma unroll
    for (int i=0;i<N;i++)
      acc = __fadd_rn(acc, __fmul_rn(kw.w[i], sv[threadIdx.y][xo + i]));
    drow[x] = acc;
  }
}

__global__ void k_down(int S){
  int idx = blockIdx.x*blockDim.x + threadIdx.x;
  int HW = S*S, tot = 2*HW; if (idx >= tot) return;
  int b = idx/HW, rem = idx-b*HW;
  int y = rem/S, x = rem-(rem/S)*S;
  int S2 = 2*S, HW2 = 4*HW;
  g_lv[0][idx] = g_lv[3][b*HW2 + (2*y)*S2 + 2*x];
}

// ---------------- FUSED hess + emap + vals + round-0 hist ----------------
// One launch per octave, z = batch. Per 32x8 tile:
//   lv tiles (halo 4, edge-clamp at load)  -> resp tiles (halo 2, -FLT_MAX OOI)
//   -> e tiles (halo 1, Cephes, 0 OOI)     -> vals + histogram.
// Every per-pixel op sequence identical to the unfused kernels -> bit-exact.
__global__ void k_hev(int H,int W,float q0,float q1,float q2,float q3,float q4){
  int b = blockIdx.z;
  int x0 = blockIdx.x*BX, y0 = blockIdx.y*BY;
  int HW = H*W;
  __shared__ float tl [5][BY+8][BX+8];
  __shared__ float trs[5][BY+4][BX+4];
  __shared__ float tee[5][BY+2][BX+2];
  __shared__ unsigned sh[256];
  int tx = threadIdx.x, ty = threadIdx.y;
  int tid = ty*BX + tx;
  sh[tid] = 0u;

  // 1) load lv tiles, edge-clamped (same as k_hess2 load)
  for (int l=0;l<5;l++){
    const float* s = &g_lv[l][(size_t)b*HW];
    for (int j = ty; j < BY+8; j += BY){
      int yy = y0 + j - 4; yy = yy<0?0:(yy>H-1?H-1:yy);
      for (int i = tx; i < BX+8; i += BX){
        int xx = x0 + i - 4; xx = xx<0?0:(xx>W-1?W-1:xx);
        tl[l][j][i] = s[yy*W+xx];
      }
    }
  }
  __syncthreads();

  // 2) resp tiles (halo 2); out-of-image -> -FLT_MAX
  for (int l=0;l<5;l++){
    float s4 = (l==0)?q0:(l==1)?q1:(l==2)?q2:(l==3)?q3:q4;
    for (int idx = tid; idx < (BY+4)*(BX+4); idx += BX*BY){
      int j = idx / (BX+4), i = idx - j*(BX+4);
      int gy = y0 + j - 2, gx = x0 + i - 2;
      float out = -3.402823466e38f;
      if (gy >= 0 && gy < H && gx >= 0 && gx < W){
        float dxx=0.f,dxy=0.f,dyy=0.f;
        #pragma unroll
        for (int ki=0;ki<5;ki++){
          #pragma unroll
          for (int kj=0;kj<5;kj++){
            float pv = tl[l][j+ki][i+kj];
            dxx = __fadd_rn(dxx, __fmul_rn(cGXX[ki*5+kj], pv));
            dxy = __fadd_rn(dxy, __fmul_rn(cGXY[ki*5+kj], pv));
            dyy = __fadd_rn(dyy, __fmul_rn(cGYY[ki*5+kj], pv));
          }
        }
        float det = __fsub_rn(__fmul_rn(dxx,dyy), __fmul_rn(dxy,dxy));
        out = __fmul_rn(det, s4);
      }
      trs[l][j][i] = out;
    }
  }
  __syncthreads();

  // 3) e tiles (halo 1); out-of-image -> 0; also write g_e for interior
  for (int l=0;l<5;l++){
    for (int idx = tid; idx < (BY+2)*(BX+2); idx += BX*BY){
      int j = idx / (BX+2), i = idx - j*(BX+2);
      int gy = y0 + j - 1, gx = x0 + i - 1;
      float ev = 0.f;
      if (gy >= 0 && gy < H && gx >= 0 && gx < W){
        float m = -3.402823466e38f;
        for (int dd=l-1; dd<=l+1; dd++){
          if (dd<0 || dd>4) continue;
          #pragma unroll
          for (int dy=-1; dy<=1; dy++)
            #pragma unroll
            for (int dx=-1; dx<=1; dx++)
              m = fmaxf(m, trs[dd][j+1+dy][i+1+dx]);
        }
        float c = trs[l][j+1][i+1];
        ev = xla_expf(__fsub_rn(c, m));
        g_e[l][(size_t)b*HW + gy*W + gx] = ev;
      }
      tee[l][j][i] = ev;
    }
  }
  __syncthreads();

  // 4) vals + fused histogram (exact (d,h,w) order; padded terms are no-ops)
  int x = x0 + tx, y = y0 + ty;
  if (x < W && y < H){
    for (int l=0;l<5;l++){
      float den=0.f, num=0.f;
      for (int dd=l-1; dd<=l+1; dd++){
        if (dd<0 || dd>4) continue;
        #pragma unroll
        for (int dy=-1; dy<=1; dy++)
          #pragma unroll
          for (int dx=-1; dx<=1; dx++){
            float ev = tee[dd][ty+1+dy][tx+1+dx];
            den = __fadd_rn(den, ev);
            num = __fadd_rn(num, __fmul_rn(ev, trs[dd][ty+2+dy][tx+2+dx]));
          }
      }
      float v = __fdiv_rn(num, __fadd_rn(den, EPSF));
      g_vals[l][(size_t)b*HW + y*W + x] = v;
      atomicAdd(&sh[fkey(v)>>24], 1u);
    }
  }
  __syncthreads();
  if (sh[tid]) atomicAdd(&g_bins[b][tid], sh[tid]);
}

// ---------------- top-k machinery ----------------
__global__ void k_compact1(int N,int HW){
  int b = blockIdx.y;
  __shared__ unsigned sdsel;
  if (threadIdx.x == 0){
    unsigned k = NFEAT, cum = 0; unsigned dsel = 0;
    for (int d=255; d>=0; d--){
      unsigned c = g_bins[b][d];
      if (cum + c >= k){ dsel = (unsigned)d; break; }
      cum += c;
    }
    sdsel = dsel;
  }
  __syncthreads();
  unsigned dsel = sdsel;
  for (int i=blockIdx.x*blockDim.x+threadIdx.x; i<N; i+=gridDim.x*blockDim.x){
    unsigned key = fkey(cand_val(0,b,(unsigned)i,HW));
    if ((key>>24) >= dsel){
      unsigned p = atomicAdd(&g_cnt1[b], 1u);
      if (p < C1CAP) g_cand1[b][p] = (unsigned)i;
    }
  }
}

__global__ void k_tail(int HW){
  int b = blockIdx.x;
  __shared__ unsigned bins[256];
  __shared__ unsigned spref, skrem, scnt;
  int tid = threadIdx.x;                 // 1024 threads
  unsigned M = g_cnt1[b]; if (M > C1CAP) M = C1CAP;
  if (tid == 0){
    unsigned k = NFEAT, cum = 0; unsigned dsel = 0;
    for (int d=255; d>=0; d--){
      unsigned c = g_bins[b][d];
      if (cum + c >= k){ dsel = (unsigned)d; break; }
      cum += c;
    }
    spref = dsel; skrem = k - cum;
  }
  __syncthreads();
  for (int r=1;r<4;r++){
    if (tid < 256) bins[tid] = 0u;
    __syncthreads();
    unsigned pref = spref;
    int shift = 24 - 8*r;
    for (unsigned i=tid; i<M; i+=1024){
      unsigned key = fkey(cand_val(0,b,g_cand1[b][i],HW));
      if ((key >> (8*(4-r))) == pref) atomicAdd(&bins[(key>>shift)&0xFFu], 1u);
    }
    __syncthreads();
    if (tid == 0){
      unsigned k = skrem, cum = 0; unsigned dsel = 0;
      for (int d=255; d>=0; d--){
        unsigned c = bins[d];
        if (cum + c >= k){ dsel = (unsigned)d; break; }
        cum += c;
      }
      spref = (spref<<8) | dsel; skrem = k - cum;
      if (r == 3) scnt = 0u;
    }
    __syncthreads();
  }
  unsigned T = spref;
  for (unsigned i=tid; i<M; i+=1024){
    unsigned idx = g_cand1[b][i];
    unsigned key = fkey(cand_val(0,b,idx,HW));
    if (key >= T){
      unsigned p = atomicAdd(&scnt, 1u);
      if (p < CANDCAP) g_candlist[b][p] = idx;
    }
  }
  __syncthreads();
  if (tid < 256) g_bins[b][tid] = 0u;    // reset for next octave / next replay
  if (tid == 0){ g_candcnt[b] = scnt; g_cnt1[b] = 0u; }
}

__global__ void k_tailf(int N){
  int b = blockIdx.x;
  __shared__ unsigned bins[256];
  __shared__ unsigned spref, skrem, scnt;
  int tid = threadIdx.x;                 // 1024
  if (tid == 0){ spref = 0u; skrem = NFEAT; }
  __syncthreads();
  for (int r=0;r<4;r++){
    if (tid < 256) bins[tid] = 0u;
    __syncthreads();
    unsigned pref = spref;
    int shift = 24 - 8*r;
    for (int i=tid; i<N; i+=1024){
      unsigned key = fkey(g_cand_resp[b][i]);
      bool ok = (r==0) || ((key >> (8*(4-r))) == pref);
      if (ok) atomicAdd(&bins[(key>>shift)&0xFFu], 1u);
    }
    __syncthreads();
    if (tid == 0){
      unsigned k = skrem, cum = 0; unsigned dsel = 0;
      for (int d=255; d>=0; d--){
        unsigned c = bins[d];
        if (cum + c >= k){ dsel = (unsigned)d; break; }
        cum += c;
      }
      spref = (spref<<8) | dsel; skrem = k - cum;
      if (r == 3) scnt = 0u;
    }
    __syncthreads();
  }
  unsigned T = spref;
  for (int i=tid; i<N; i+=1024){
    unsigned key = fkey(g_cand_resp[b][i]);
    if (key >= T){
      unsigned p = atomicAdd(&scnt, 1u);
      if (p < CANDCAP) g_candlist[b][p] = (unsigned)i;
    }
  }
  __syncthreads();
  if (tid < 256) g_bins[b][tid] = 0u;
  if (tid == 0){ g_candcnt[b] = scnt; g_cnt1[b] = 0u; }
}

__global__ void k_sortsel(int mode,int HW,int outmode){
  __shared__ unsigned long long s[SORTN];
  int b = blockIdx.x;
  unsigned M = g_candcnt[b]; if (M > CANDCAP) M = CANDCAP;
  for (int t=threadIdx.x; t<SORTN; t+=blockDim.x){
    unsigned long long kv = 0ULL;
    if (t < (int)M){
      unsigned i = g_candlist[b][t];
      kv = ((unsigned long long)fkey(cand_val(mode,b,i,HW)) << 32) | (unsigned)(~i);
    }
    s[t] = kv;
  }
  __syncthreads();
  for (int k=2; k<=SORTN; k<<=1){
    for (int j=k>>1; j>0; j>>=1){
      for (int i=threadIdx.x; i<SORTN; i+=blockDim.x){
        int p = i ^ j;
        if (p > i){
          unsigned long long a=s[i], c=s[p];
          bool up = ((i & k) == 0);
          if (up ? (a < c) : (a > c)){ s[i]=c; s[p]=a; }
        }
      }
      __syncthreads();
    }
  }
  for (int t=threadIdx.x; t<NFEAT; t+=blockDim.x){
    unsigned i = ~((unsigned)(s[t] & 0xFFFFFFFFULL));
    float v = cand_val(mode,b,i,HW);
    if (outmode==0){ g_selidx[b][t]=i; g_selval[b][t]=v; }
    else           { g_finidx[b][t]=i; g_finval[b][t]=v; }
  }
}

__global__ void k_laf(int H,int W,int count,int use_sel,int base){
  int j = blockIdx.x*blockDim.x + threadIdx.x;
  int b = blockIdx.y;
  if (j >= count) return;
  int HW = H*W;
  unsigned idx; float v;
  if (use_sel){ idx = g_selidx[b][j]; v = g_selval[b][j]; }
  else {
    idx = (unsigned)j;
    unsigned d0 = idx/(unsigned)HW;
    v = g_vals[d0][(unsigned)b*HW + (idx - d0*(unsigned)HW)];
  }
  int d = idx/HW, rem = idx-d*HW;
  int y = rem/W, x = rem-(rem/W)*W;
  float den=0.f, sd=0.f, sx=0.f, sy=0.f;
  for (int dd=d-1; dd<=d+1; dd++){
    if (dd<0 || dd>4) continue;
    const float* e = &g_e[dd][b*HW];
    for (int yy=y-1; yy<=y+1; yy++){
      if ((unsigned)yy >= (unsigned)H) continue;
      for (int xx=x-1; xx<=x+1; xx++){
        if ((unsigned)xx >= (unsigned)W) continue;
        float ev = e[yy*W+xx];
        den = __fadd_rn(den, ev);
        if (dd != d) sd = __fadd_rn(sd, __fmul_rn(ev, (float)(dd-d)));
        if (xx != x) sx = __fadd_rn(sx, __fmul_rn(ev, (float)(xx-x)));
        if (yy != y) sy = __fadd_rn(sy, __fmul_rn(ev, (float)(yy-y)));
      }
    }
  }
  float dE = __fadd_rn(den, EPSF);
  float cd = __fadd_rn(__fdiv_rn(sd,dE), (float)d);
  float cx = __fadd_rn(__fdiv_rn(sx,dE), (float)x);
  float cy = __fadd_rn(__fdiv_rn(sy,dE), (float)y);
  float scale = __fmul_rn(1.6f, (float)exp2((double)__fdiv_rn(cd, 3.0f)));
  float s6 = __fmul_rn(6.0f, scale);
  float g = ((__fsub_rn(cx,s6) > 0.f) && (__fadd_rn(cx,s6) < (float)(W-1)) &&
             (__fsub_rn(cy,s6) > 0.f) && (__fadd_rn(cy,s6) < (float)(H-1))) ? 1.f : 0.f;
  float mn = (float)(H < W ? H : W);
  int o = base + j;
  g_cand_resp[b][o] = __fmul_rn(v, g);
  float* Lf = g_cand_laf[b][o];
  Lf[0] = __fdiv_rn(s6,mn); Lf[1] = 0.f; Lf[2] = __fdiv_rn(cx,(float)W);
  Lf[3] = 0.f;              Lf[4] = __fdiv_rn(s6,mn); Lf[5] = __fdiv_rn(cy,(float)H);
}

__global__ void k_out(float* __restrict__ out){
  int t = blockIdx.x*blockDim.x + threadIdx.x;
  if (t >= 2*NFEAT) return;
  int b = t/NFEAT, j = t-b*NFEAT;
  unsigned i = g_finidx[b][j];
  const float* L = g_cand_laf[b][i];
  float* o = out + (b*NFEAT + j)*6;
  #pragma unroll
  for (int e=0;e<6;e++) o[e] = __fmul_rn(L[e], 1024.0f);
  out[2*NFEAT*6 + b*NFEAT + j] = g_finval[b][j];
}

// ---------------- host ----------------
static void launch_blur(const float* src, float* dst, int S, const KW& kw, int n){
  dim3 g((S+127)/128, (S+7)/8, 2);
  dim3 tb(32, 8);
  switch(n){
    case 9:  k_blur3<9 ><<<g,tb>>>(src,dst,S,S,kw); break;
    case 11: k_blur3<11><<<g,tb>>>(src,dst,S,S,kw); break;
    case 13: k_blur3<13><<<g,tb>>>(src,dst,S,S,kw); break;
    case 15: k_blur3<15><<<g,tb>>>(src,dst,S,S,kw); break;
    case 17: k_blur3<17><<<g,tb>>>(src,dst,S,S,kw); break;
    case 19: k_blur3<19><<<g,tb>>>(src,dst,S,S,kw); break;
    default: k_blur3<21><<<g,tb>>>(src,dst,S,S,kw); break;
  }
}

extern "C" void kernel_launch(void* const* d_in, const int* in_sizes, int n_in,
                              void* d_out, int out_size){
  (void)in_sizes; (void)n_in; (void)out_size;
  const float* img = (const float*)d_in[0];
  float* out = (float*)d_out;

  float *p_lv = 0;
  cudaGetSymbolAddress((void**)&p_lv, g_lv);

  double step = pow(2.0, 1.0/3.0);
  double q = sqrt(step*step - 1.0);
  double sgm[5]; int ksz[5];
  sgm[0] = sqrt(1.6*1.6 - 0.25);
  { double cs = 1.6; for (int i=1;i<5;i++){ sgm[i] = cs * q; cs *= step; } }
  for (int i=0;i<5;i++){ int k=(int)(8.0*sgm[i]+1.0); if(!(k&1))k++; ksz[i]=k; }
  float s4[5];
  { double cs = 1.6;
    for (int l=0;l<5;l++){ float sgf=(float)cs; s4[l]=powf(sgf,4.0f); cs*=step; } }

  // host weight pipeline: identical f32 op sequence (volatile blocks reassociation)
  KW kws[5];
  for (int t=0;t<5;t++){
    int n = ksz[t], h = n/2;
    volatile float den2 = (float)(2.0*sgm[t]*sgm[t]);
    float w[32];
    for (int i=0;i<n;i++){
      volatile float x = (float)(i - h);
      volatile float arg = -(x*x)/den2;
      w[i] = (float)exp((double)arg);
    }
    volatile float r[8];
    for (int j=0;j<8;j++) r[j] = w[j];
    int i = 8;
    for (; i + 8 <= n; i += 8)
      for (int j=0;j<8;j++) r[j] = r[j] + w[i+j];
    volatile float s01 = r[0]+r[1], s23 = r[2]+r[3], s45 = r[4]+r[5], s67 = r[6]+r[7];
    volatile float s0123 = s01+s23, s4567 = s45+s67;
    volatile float sum = s0123 + s4567;
    for (; i < n; i++) sum = sum + w[i];
    for (int k2=0;k2<24;k2++) kws[t].w[k2] = 0.f;
    for (int k2=0;k2<n;k2++) kws[t].w[k2] = w[k2]/sum;
  }

  static const int SS[7] = {1024,512,256,128,64,32,16};
  int base = 0;
  for (int o=0;o<7;o++){
    int S = SS[o], HW = S*S, tot = 2*HW;
    if (o == 0){
      launch_blur(img, p_lv, S, kws[0], ksz[0]);
    } else {
      int thr = 256, blk = (tot+thr-1)/thr;
      k_down<<<blk,thr>>>(S);
    }
    for (int i=1;i<5;i++)
      launch_blur(p_lv+(i-1)*LVS, p_lv+i*LVS, S, kws[i], ksz[i]);

    dim3 tg((S+BX-1)/BX, (S+BY-1)/BY, 2);
    dim3 tb(BX, BY);
    k_hev<<<tg,tb>>>(S,S,s4[0],s4[1],s4[2],s4[3],s4[4]);

    int N = 5*HW;
    if (N > NFEAT){
      int hb = (N+255)/256; if (hb > 2048) hb = 2048;
      k_compact1<<<dim3(hb,2),256>>>(N,HW);     // self round-0 scan + compact
      k_tail<<<2,1024>>>(HW);                   // rounds 1-3 + compact + reset
      k_sortsel<<<2,512>>>(0,HW,0);
      k_laf<<<dim3((NFEAT+127)/128,2),128>>>(S,S,NFEAT,1,base);
      base += NFEAT;
    } else {
      k_laf<<<dim3((N+127)/128,2),128>>>(S,S,N,0,base);
      base += N;
    }
  }

  // final selection over all candidates (base == 13280), fully fused
  k_tailf<<<2,1024>>>(base);
  k_sortsel<<<2,512>>>(1,0,1);
  k_out<<<(2*NFEAT+255)/256,256>>>(out);
}